// round 16
// baseline (speedup 1.0000x reference)
#include <cuda_runtime.h>
#include <cuda_fp16.h>
#include <cstdint>

#define DIN   256
#define DH    512
#define NB    256
#define KW    768            // K per Winograd point
#define MTOT  2048
#define NT2   4096           // 256 imgs * 16 tiles
#define BK    256            // K per stage (four 64-K subtiles)
#define NKC   3              // K chunks per point (768/256)
#define NCH   (16*NKC)       // 48 global chunks
#define GT    256
#define STG   98304          // A 64KB + B 32KB per stage
#define SMEM_BYTES (2*STG)   // 196608
#define PREPA_BLOCKS 6144
#define PREPB_BLOCKS 2048

__device__ __align__(16) __half g_Aw[(size_t)16*MTOT*KW];   // [p][m][k]
__device__ __align__(16) __half g_Bw[(size_t)16*NT2*KW];    // [p][col][k]

__device__ __forceinline__ uint32_t smem_u32(const void* p) {
    uint32_t a;
    asm("{ .reg .u64 t; cvta.to.shared.u64 t, %1; cvt.u32.u64 %0, t; }" : "=r"(a) : "l"(p));
    return a;
}
__device__ __forceinline__ void cp16(uint32_t dst, const void* src) {
    asm volatile("cp.async.cg.shared.global [%0], [%1], 16;" :: "r"(dst), "l"(src));
}
__device__ __forceinline__ void cp_commit() { asm volatile("cp.async.commit_group;"); }
template<int N> __device__ __forceinline__ void cp_wait() {
    asm volatile("cp.async.wait_group %0;" :: "n"(N));
}
__device__ __forceinline__ void ldsm4(uint32_t* r, uint32_t a) {
    asm volatile("ldmatrix.sync.aligned.m8n8.x4.shared.b16 {%0,%1,%2,%3}, [%4];"
                 : "=r"(r[0]), "=r"(r[1]), "=r"(r[2]), "=r"(r[3]) : "r"(a));
}
__device__ __forceinline__ void mma_f16(float* d, const uint32_t* a, const uint32_t* b) {
    asm volatile(
        "mma.sync.aligned.m16n8k16.row.col.f32.f16.f16.f32 "
        "{%0,%1,%2,%3}, {%4,%5,%6,%7}, {%8,%9}, {%0,%1,%2,%3};"
        : "+f"(d[0]), "+f"(d[1]), "+f"(d[2]), "+f"(d[3])
        : "r"(a[0]), "r"(a[1]), "r"(a[2]), "r"(a[3]), "r"(b[0]), "r"(b[1]));
}

// ---- merged prep: blocks [0,6144) weights->U, [6144,8192) im2col->V ----
__global__ void prep_all(
    const float* __restrict__ x,   const float* __restrict__ hs,
    const float* __restrict__ wii, const float* __restrict__ wif_,
    const float* __restrict__ wig, const float* __restrict__ wio,
    const float* __restrict__ whi, const float* __restrict__ whf,
    const float* __restrict__ whg, const float* __restrict__ who)
{
    __shared__ float sd[96][100];
    const int bx = blockIdx.x;
    const int tid = threadIdx.x;

    if (bx < PREPA_BLOCKS) {
        size_t idx = (size_t)bx * 256 + tid;
        int m = (int)(idx / KW);
        int cin = (int)(idx - (size_t)m * KW);
        int cb = m >> 7, g = (m >> 5) & 3, cl = m & 31;
        int c = cb * 32 + cl;
        const float* wx = (g == 0) ? wii : (g == 1) ? wif_ : (g == 2) ? wig : wio;
        const float* wh = (g == 0) ? whi : (g == 1) ? whf : (g == 2) ? whg : who;
        const float* w9 = (cin < DIN) ? (wx + ((size_t)c * DIN + cin) * 9)
                                      : (wh + ((size_t)c * DH + (cin - DIN)) * 9);
        float gw[3][3];
#pragma unroll
        for (int i = 0; i < 9; i++) gw[i / 3][i % 3] = w9[i];
        float W[4][3];
#pragma unroll
        for (int l = 0; l < 3; l++) {
            W[0][l] = gw[0][l];
            W[1][l] = 0.5f * (gw[0][l] + gw[1][l] + gw[2][l]);
            W[2][l] = 0.5f * (gw[0][l] - gw[1][l] + gw[2][l]);
            W[3][l] = gw[2][l];
        }
#pragma unroll
        for (int i = 0; i < 4; i++) {
            float U[4];
            U[0] = W[i][0];
            U[1] = 0.5f * (W[i][0] + W[i][1] + W[i][2]);
            U[2] = 0.5f * (W[i][0] - W[i][1] + W[i][2]);
            U[3] = W[i][2];
#pragma unroll
            for (int j = 0; j < 4; j++)
                g_Aw[((size_t)(i * 4 + j) * MTOT + m) * KW + cin] = __float2half(U[j]);
        }
        return;
    }

    const int bb  = bx - PREPA_BLOCKS;
    const int img = bb >> 3;
    const int ch  = bb & 7;
    for (int i = tid; i < 96 * 100; i += blockDim.x) {
        int ci = i / 100, pp = i - ci * 100;
        int yy = pp / 10, xx = pp - yy * 10;
        int ry = (yy == 0) ? 1 : ((yy == 9) ? 6 : yy - 1);
        int rx = (xx == 0) ? 1 : ((xx == 9) ? 6 : xx - 1);
        int cg = ch * 96 + ci;
        const float* src = (cg < DIN)
            ? x  + ((size_t)img * DIN + cg) * 64
            : hs + (((size_t)img * 2) * DH + (cg - DIN)) * 64;
        sd[ci][pp] = src[ry * 8 + rx];
    }
    __syncthreads();
    for (int e = tid; e < 96 * 16; e += blockDim.x) {
        int ci = e % 96, t = e / 96;
        int ty = t >> 2, tx = t & 3;
        int cg = ch * 96 + ci;
        float d[4][4];
#pragma unroll
        for (int k = 0; k < 4; k++)
#pragma unroll
            for (int l = 0; l < 4; l++)
                d[k][l] = sd[ci][(2 * ty + k) * 10 + 2 * tx + l];
        float W[4][4];
#pragma unroll
        for (int l = 0; l < 4; l++) {
            W[0][l] = d[0][l] - d[2][l];
            W[1][l] = d[1][l] + d[2][l];
            W[2][l] = d[2][l] - d[1][l];
            W[3][l] = d[1][l] - d[3][l];
        }
        size_t col = (size_t)img * 16 + t;
#pragma unroll
        for (int i = 0; i < 4; i++) {
            float V[4];
            V[0] = W[i][0] - W[i][2];
            V[1] = W[i][1] + W[i][2];
            V[2] = W[i][2] - W[i][1];
            V[3] = W[i][1] - W[i][3];
#pragma unroll
            for (int j = 0; j < 4; j++)
                g_Bw[((size_t)(i * 4 + j) * NT2 + col) * KW + cg] = __float2half(V[j]);
        }
    }
}

// ---- fused GEMM + inverse transform + LSTM (BK=256, 2-stage, 1 barrier/chunk) ----
__global__ void __launch_bounds__(GT, 1) gemm_fused(
    const float* __restrict__ hs,
    const float* __restrict__ bi, const float* __restrict__ bf_,
    const float* __restrict__ bg, const float* __restrict__ bo,
    const float* __restrict__ wci, const float* __restrict__ wcf,
    const float* __restrict__ wco, float* __restrict__ out)
{
    extern __shared__ char smem[];
    const uint32_t sb = smem_u32(smem);
    const int tid = threadIdx.x;
    const int wid = tid >> 5, lane = tid & 31;
    const int wm = wid & 3, wn = wid >> 2;    // 4x2 warps, warp tile 32x32
    const int mt = blockIdx.x, nt = blockIdx.y;
    const int m0 = mt * 128, n0 = nt * 64;

    float outr[2][4][4][4];                   // [mi][j=nj*2+s][v][a*2+b]
#pragma unroll
    for (int i = 0; i < 2; i++)
#pragma unroll
        for (int j = 0; j < 4; j++)
#pragma unroll
            for (int v = 0; v < 4; v++)
#pragma unroll
                for (int q = 0; q < 4; q++) outr[i][j][v][q] = 0.f;

    // stage layout: A 4 x 16KB subtiles (k64 each), then B 4 x 8KB at +65536
    // part in 0..3: issue 1536 cp16s (6/thread)
    auto issue_part = [&](int cc, int part) {
        const uint32_t st = sb + (cc & 1) * STG;
        int p = cc / NKC, kc = cc - p * NKC;
        const __half* Ap = g_Aw + (size_t)p * MTOT * KW;
        const __half* Bp = g_Bw + (size_t)p * NT2 * KW;
        const size_t kof = (size_t)kc * BK;
        const int lo = part * 1536, hi = lo + 1536;
#pragma unroll
        for (int i = tid + lo; i < hi; i += GT) {
            uint32_t dst; const __half* src;
            if (i < 4096) {                  // A: 4 subtiles x 128 rows x 8 chunks
                int kh = i >> 10, j = i & 1023, r = j >> 3, c = j & 7;
                src = Ap + (size_t)(m0 + r) * KW + kof + kh * 64 + c * 8;
                dst = st + kh * 16384 + r * 128 + ((c ^ (r & 7)) << 4);
            } else {                         // B: 4 subtiles x 64 rows x 8 chunks
                int j = i - 4096;
                int kh = j >> 9, jj = j & 511, r = jj >> 3, c = jj & 7;
                src = Bp + (size_t)(n0 + r) * KW + kof + kh * 64 + c * 8;
                dst = st + 65536 + kh * 8192 + r * 128 + ((c ^ (r & 7)) << 4);
            }
            cp16(dst, src);
        }
    };

    // fragment loader for flattened k16 step kkk (0..15) within a stage
    auto load_frags = [&](uint32_t st, int kkk, uint32_t af[2][4], uint32_t bf[2][4]) {
        const uint32_t sa  = st + (kkk >> 2) * 16384;
        const uint32_t sbb = st + 65536 + (kkk >> 2) * 8192;
        const int kk = kkk & 3;
#pragma unroll
        for (int mi = 0; mi < 2; mi++) {
            int r = wm * 32 + mi * 16 + (lane & 15);
            int c = kk * 2 + (lane >> 4);
            ldsm4(af[mi], sa + r * 128 + ((c ^ (r & 7)) << 4));
        }
#pragma unroll
        for (int nj = 0; nj < 2; nj++) {
            int r = wn * 32 + nj * 16 + (lane & 7) + ((lane >> 4) << 3);
            int c = kk * 2 + ((lane >> 3) & 1);
            ldsm4(bf[nj], sbb + r * 128 + ((c ^ (r & 7)) << 4));
        }
    };

    // prologue: stage 0 fully issued + committed
    issue_part(0, 0); issue_part(0, 1); issue_part(0, 2); issue_part(0, 3);
    cp_commit();

    for (int p = 0; p < 16; p++) {
        float acc[2][4][4];                   // [mi][nj*2+s][v]
#pragma unroll
        for (int i = 0; i < 2; i++)
#pragma unroll
            for (int j = 0; j < 4; j++)
#pragma unroll
                for (int v = 0; v < 4; v++) acc[i][j][v] = 0.f;

        for (int kc = 0; kc < NKC; kc++) {
            int cc = p * NKC + kc;
            cp_wait<0>();                     // stage cc complete (sole group)
            __syncthreads();                  // all threads done with buffer (cc+1)&1

            const uint32_t st = sb + (cc & 1) * STG;
            uint32_t a_f[2][2][4], b_f[2][2][4];   // double-buffered fragments
            load_frags(st, 0, a_f[0], b_f[0]);
#pragma unroll
            for (int kkk = 0; kkk < 16; kkk++) {
                const int cur = kkk & 1;
                if (kkk < 15) load_frags(st, kkk + 1, a_f[cur ^ 1], b_f[cur ^ 1]);
#pragma unroll
                for (int mi = 0; mi < 2; mi++)
#pragma unroll
                    for (int nj = 0; nj < 2; nj++) {
                        mma_f16(acc[mi][nj * 2],     a_f[cur][mi], &b_f[cur][nj][0]);
                        mma_f16(acc[mi][nj * 2 + 1], a_f[cur][mi], &b_f[cur][nj][2]);
                    }
                // spread next-stage cp issue over kkk 0..3; buffer (cc+1)&1
                // was released by this chunk's top barrier
                if (kkk < 4 && cc + 1 < NCH) {
                    issue_part(cc + 1, kkk);
                    if (kkk == 3) cp_commit();
                }
            }
        }

        // inverse-transform coefficients for point p = (i,j)
        int pi_ = p >> 2, pj = p & 3;
        float ca0 = (pi_ == 3) ? 0.f : 1.f;                       // At row0 = 1,1,1,0
        float ca1 = (pi_ == 0) ? 0.f : ((pi_ == 1) ? 1.f : -1.f); // At row1 = 0,1,-1,-1
        float cb0 = (pj  == 3) ? 0.f : 1.f;
        float cb1 = (pj  == 0) ? 0.f : ((pj  == 1) ? 1.f : -1.f);
        float c00 = ca0 * cb0, c01 = ca0 * cb1, c10 = ca1 * cb0, c11 = ca1 * cb1;
#pragma unroll
        for (int mi = 0; mi < 2; mi++)
#pragma unroll
            for (int j = 0; j < 4; j++)
#pragma unroll
                for (int v = 0; v < 4; v++) {
                    float m = acc[mi][j][v];
                    outr[mi][j][v][0] += c00 * m;
                    outr[mi][j][v][1] += c01 * m;
                    outr[mi][j][v][2] += c10 * m;
                    outr[mi][j][v][3] += c11 * m;
                }
    }

    // ---- epilogue: outr -> pre2[4 imgs][128][66], then LSTM ----
    __syncthreads();
    float* pre2 = (float*)smem;
    const int lr = lane >> 2, lc = (lane & 3) * 2;
#pragma unroll
    for (int mi = 0; mi < 2; mi++)
#pragma unroll
        for (int j = 0; j < 4; j++)
#pragma unroll
            for (int v = 0; v < 4; v++) {
                int nj = j >> 1, s = j & 1;
                int row = wm * 32 + mi * 16 + lr + ((v >> 1) << 3);
                int col = wn * 32 + nj * 16 + s * 8 + lc + (v & 1);
                int img = col >> 4, t = col & 15;
                int ty = t >> 2, tx = t & 3;
                float* dst = &pre2[((img * 128) + row) * 66 + (2 * ty) * 8 + 2 * tx];
                dst[0] = outr[mi][j][v][0];
                dst[1] = outr[mi][j][v][1];
                dst[8] = outr[mi][j][v][2];
                dst[9] = outr[mi][j][v][3];
            }
    __syncthreads();

    const size_t base2 = (size_t)NB * DH * 64;
    for (int e = tid; e < 4 * 32 * 64; e += GT) {
        int img = e >> 11, cl = (e >> 6) & 31, pix = e & 63;
        int n = nt * 4 + img;
        int c = mt * 32 + cl;
        const float* pr = &pre2[(size_t)img * 128 * 66];
        const float* c0p = hs + ((size_t)(n * 2) + 1) * DH * 64;
        float pi = pr[(cl)      * 66 + pix] + bi[c];
        float pf = pr[(32 + cl) * 66 + pix] + bf_[c];
        float pg = pr[(64 + cl) * 66 + pix] + bg[c];
        float po = pr[(96 + cl) * 66 + pix] + bo[c];
        float c0 = c0p[(size_t)c * 64 + pix];
        float ig = 1.f / (1.f + expf(-(pi + c0 * wci[c * 64 + pix])));
        float fg = 1.f / (1.f + expf(-(pf + c0 * wcf[c * 64 + pix])));
        float gg = tanhf(pg);
        float ct = fg * c0 + ig * gg;
        float og = 1.f / (1.f + expf(-(po + ct * wco[c * 64 + pix])));
        float ht = og * tanhf(ct);
        out[((size_t)n * DH + c) * 64 + pix] = og;
        out[base2 + (((size_t)n * 2) * DH + c) * 64 + pix] = ht;
        out[base2 + (((size_t)n * 2 + 1) * DH + c) * 64 + pix] = ct;
    }
}

extern "C" void kernel_launch(void* const* d_in, const int* in_sizes, int n_in,
                              void* d_out, int out_size) {
    (void)in_sizes; (void)n_in; (void)out_size;
    const float* x  = (const float*)d_in[0];
    const float* hs = (const float*)d_in[1];

    cudaFuncSetAttribute(gemm_fused, cudaFuncAttributeMaxDynamicSharedMemorySize,
                         SMEM_BYTES);

    prep_all<<<PREPA_BLOCKS + PREPB_BLOCKS, 256>>>(
        x, hs,
        (const float*)d_in[2], (const float*)d_in[3], (const float*)d_in[4],
        (const float*)d_in[5], (const float*)d_in[6], (const float*)d_in[7],
        (const float*)d_in[8], (const float*)d_in[9]);

    dim3 grid(MTOT / 128, NT2 / 64);   // 16 x 64 = 1024 CTAs
    gemm_fused<<<grid, GT, SMEM_BYTES>>>(
        hs,
        (const float*)d_in[10], (const float*)d_in[11],
        (const float*)d_in[12], (const float*)d_in[13],
        (const float*)d_in[14], (const float*)d_in[15], (const float*)d_in[16],
        (float*)d_out);
}

// round 17
// speedup vs baseline: 1.0563x; 1.0563x over previous
#include <cuda_runtime.h>
#include <cuda_fp16.h>
#include <cstdint>

#define DIN   256
#define DH    512
#define NB    256
#define KW    768            // K per Winograd point
#define MTOT  2048
#define NT2   4096           // 256 imgs * 16 tiles
#define BK    128            // K per stage (two 64-K subtiles)
#define NKC   6              // K chunks per point (768/128)
#define NCH   (16*NKC)       // 96 global chunks
#define GT    256
#define STG   49152          // A 32KB + B 16KB per stage
#define SMEM_BYTES (4*STG)   // 196608
#define PREPA_BLOCKS 6144
#define PREPB_BLOCKS 2048

__device__ __align__(16) __half g_Aw[(size_t)16*MTOT*KW];   // [p][m][k]
__device__ __align__(16) __half g_Bw[(size_t)16*NT2*KW];    // [p][col][k]

__device__ __forceinline__ uint32_t smem_u32(const void* p) {
    uint32_t a;
    asm("{ .reg .u64 t; cvta.to.shared.u64 t, %1; cvt.u32.u64 %0, t; }" : "=r"(a) : "l"(p));
    return a;
}
__device__ __forceinline__ void cp16(uint32_t dst, const void* src) {
    asm volatile("cp.async.cg.shared.global [%0], [%1], 16;" :: "r"(dst), "l"(src));
}
__device__ __forceinline__ void cp_commit() { asm volatile("cp.async.commit_group;"); }
template<int N> __device__ __forceinline__ void cp_wait() {
    asm volatile("cp.async.wait_group %0;" :: "n"(N));
}
__device__ __forceinline__ void ldsm4(uint32_t* r, uint32_t a) {
    asm volatile("ldmatrix.sync.aligned.m8n8.x4.shared.b16 {%0,%1,%2,%3}, [%4];"
                 : "=r"(r[0]), "=r"(r[1]), "=r"(r[2]), "=r"(r[3]) : "r"(a));
}
__device__ __forceinline__ void mma_f16(float* d, const uint32_t* a, const uint32_t* b) {
    asm volatile(
        "mma.sync.aligned.m16n8k16.row.col.f32.f16.f16.f32 "
        "{%0,%1,%2,%3}, {%4,%5,%6,%7}, {%8,%9}, {%0,%1,%2,%3};"
        : "+f"(d[0]), "+f"(d[1]), "+f"(d[2]), "+f"(d[3])
        : "r"(a[0]), "r"(a[1]), "r"(a[2]), "r"(a[3]), "r"(b[0]), "r"(b[1]));
}

// ---- merged prep: blocks [0,6144) weights->U, [6144,8192) im2col->V ----
__global__ void prep_all(
    const float* __restrict__ x,   const float* __restrict__ hs,
    const float* __restrict__ wii, const float* __restrict__ wif_,
    const float* __restrict__ wig, const float* __restrict__ wio,
    const float* __restrict__ whi, const float* __restrict__ whf,
    const float* __restrict__ whg, const float* __restrict__ who)
{
    __shared__ float sd[96][100];
    const int bx = blockIdx.x;
    const int tid = threadIdx.x;

    if (bx < PREPA_BLOCKS) {
        size_t idx = (size_t)bx * 256 + tid;
        int m = (int)(idx / KW);
        int cin = (int)(idx - (size_t)m * KW);
        int cb = m >> 7, g = (m >> 5) & 3, cl = m & 31;
        int c = cb * 32 + cl;
        const float* wx = (g == 0) ? wii : (g == 1) ? wif_ : (g == 2) ? wig : wio;
        const float* wh = (g == 0) ? whi : (g == 1) ? whf : (g == 2) ? whg : who;
        const float* w9 = (cin < DIN) ? (wx + ((size_t)c * DIN + cin) * 9)
                                      : (wh + ((size_t)c * DH + (cin - DIN)) * 9);
        float gw[3][3];
#pragma unroll
        for (int i = 0; i < 9; i++) gw[i / 3][i % 3] = w9[i];
        float W[4][3];
#pragma unroll
        for (int l = 0; l < 3; l++) {
            W[0][l] = gw[0][l];
            W[1][l] = 0.5f * (gw[0][l] + gw[1][l] + gw[2][l]);
            W[2][l] = 0.5f * (gw[0][l] - gw[1][l] + gw[2][l]);
            W[3][l] = gw[2][l];
        }
#pragma unroll
        for (int i = 0; i < 4; i++) {
            float U[4];
            U[0] = W[i][0];
            U[1] = 0.5f * (W[i][0] + W[i][1] + W[i][2]);
            U[2] = 0.5f * (W[i][0] - W[i][1] + W[i][2]);
            U[3] = W[i][2];
#pragma unroll
            for (int j = 0; j < 4; j++)
                g_Aw[((size_t)(i * 4 + j) * MTOT + m) * KW + cin] = __float2half(U[j]);
        }
        return;
    }

    const int bb  = bx - PREPA_BLOCKS;
    const int img = bb >> 3;
    const int ch  = bb & 7;
    for (int i = tid; i < 96 * 100; i += blockDim.x) {
        int ci = i / 100, pp = i - ci * 100;
        int yy = pp / 10, xx = pp - yy * 10;
        int ry = (yy == 0) ? 1 : ((yy == 9) ? 6 : yy - 1);
        int rx = (xx == 0) ? 1 : ((xx == 9) ? 6 : xx - 1);
        int cg = ch * 96 + ci;
        const float* src = (cg < DIN)
            ? x  + ((size_t)img * DIN + cg) * 64
            : hs + (((size_t)img * 2) * DH + (cg - DIN)) * 64;
        sd[ci][pp] = src[ry * 8 + rx];
    }
    __syncthreads();
    for (int e = tid; e < 96 * 16; e += blockDim.x) {
        int ci = e % 96, t = e / 96;
        int ty = t >> 2, tx = t & 3;
        int cg = ch * 96 + ci;
        float d[4][4];
#pragma unroll
        for (int k = 0; k < 4; k++)
#pragma unroll
            for (int l = 0; l < 4; l++)
                d[k][l] = sd[ci][(2 * ty + k) * 10 + 2 * tx + l];
        float W[4][4];
#pragma unroll
        for (int l = 0; l < 4; l++) {
            W[0][l] = d[0][l] - d[2][l];
            W[1][l] = d[1][l] + d[2][l];
            W[2][l] = d[2][l] - d[1][l];
            W[3][l] = d[1][l] - d[3][l];
        }
        size_t col = (size_t)img * 16 + t;
#pragma unroll
        for (int i = 0; i < 4; i++) {
            float V[4];
            V[0] = W[i][0] - W[i][2];
            V[1] = W[i][1] + W[i][2];
            V[2] = W[i][2] - W[i][1];
            V[3] = W[i][1] - W[i][3];
#pragma unroll
            for (int j = 0; j < 4; j++)
                g_Bw[((size_t)(i * 4 + j) * NT2 + col) * KW + cg] = __float2half(V[j]);
        }
    }
}

// ---- fused GEMM + inverse transform + LSTM (4x2 warps, cross-chunk preload) ----
__global__ void __launch_bounds__(GT, 1) gemm_fused(
    const float* __restrict__ hs,
    const float* __restrict__ bi, const float* __restrict__ bf_,
    const float* __restrict__ bg, const float* __restrict__ bo,
    const float* __restrict__ wci, const float* __restrict__ wcf,
    const float* __restrict__ wco, float* __restrict__ out)
{
    extern __shared__ char smem[];
    const uint32_t sb = smem_u32(smem);
    const int tid = threadIdx.x;
    const int wid = tid >> 5, lane = tid & 31;
    const int wm = wid & 3, wn = wid >> 2;    // 4x2 warps, warp tile 32x32
    const int mt = blockIdx.x, nt = blockIdx.y;
    const int m0 = mt * 128, n0 = nt * 64;

    float outr[2][4][4][4];                   // [mi][j=nj*2+s][v][a*2+b]
#pragma unroll
    for (int i = 0; i < 2; i++)
#pragma unroll
        for (int j = 0; j < 4; j++)
#pragma unroll
            for (int v = 0; v < 4; v++)
#pragma unroll
                for (int q = 0; q < 4; q++) outr[i][j][v][q] = 0.f;

    // one stage = two 64-K subtiles: [A0 16K][A1 16K][B0 8K][B1 8K]
    auto issue_stage = [&](int cc, int buf) {
        const uint32_t st = sb + buf * STG;
        int p = cc / NKC, kc = cc - p * NKC;
        const __half* Ap = g_Aw + (size_t)p * MTOT * KW;
        const __half* Bp = g_Bw + (size_t)p * NT2 * KW;
        const size_t kof = (size_t)kc * BK;
#pragma unroll
        for (int i = tid; i < 3072; i += GT) {
            uint32_t dst; const __half* src;
            if (i < 2048) {                  // A: 2 subtiles x 128 rows x 8 chunks
                int kh = i >> 10, j = i & 1023, r = j >> 3, c = j & 7;
                src = Ap + (size_t)(m0 + r) * KW + kof + kh * 64 + c * 8;
                dst = st + kh * 16384 + r * 128 + ((c ^ (r & 7)) << 4);
            } else {                         // B: 2 subtiles x 64 rows x 8 chunks
                int j = i - 2048;
                int kh = j >> 9, jj = j & 511, r = jj >> 3, c = jj & 7;
                src = Bp + (size_t)(n0 + r) * KW + kof + kh * 64 + c * 8;
                dst = st + 32768 + kh * 8192 + r * 128 + ((c ^ (r & 7)) << 4);
            }
            cp16(dst, src);
        }
        cp_commit();
    };

    // fragment loader for flattened k16 step kkk (0..7) within a stage
    auto load_frags = [&](uint32_t st, int kkk, uint32_t af[2][4], uint32_t bf[2][4]) {
        const uint32_t sa  = st + (kkk >> 2) * 16384;
        const uint32_t sbb = st + 32768 + (kkk >> 2) * 8192;
        const int kk = kkk & 3;
#pragma unroll
        for (int mi = 0; mi < 2; mi++) {
            int r = wm * 32 + mi * 16 + (lane & 15);
            int c = kk * 2 + (lane >> 4);
            ldsm4(af[mi], sa + r * 128 + ((c ^ (r & 7)) << 4));
        }
#pragma unroll
        for (int nj = 0; nj < 2; nj++) {
            int r = wn * 32 + nj * 16 + (lane & 7) + ((lane >> 4) << 3);
            int c = kk * 2 + ((lane >> 3) & 1);
            ldsm4(bf[nj], sbb + r * 128 + ((c ^ (r & 7)) << 4));
        }
    };

    issue_stage(0, 0);
    issue_stage(1, 1);
    issue_stage(2, 2);

    uint32_t a_f[2][2][4], b_f[2][2][4];      // persistent double-buffered frags
    cp_wait<2>();                              // stage 0 resident
    __syncthreads();
    load_frags(sb, 0, a_f[0], b_f[0]);         // preload (cc=0, kkk=0)

    for (int p = 0; p < 16; p++) {
        float acc[2][4][4];                   // [mi][nj*2+s][v]
#pragma unroll
        for (int i = 0; i < 2; i++)
#pragma unroll
            for (int j = 0; j < 4; j++)
#pragma unroll
                for (int v = 0; v < 4; v++) acc[i][j][v] = 0.f;

        for (int kc = 0; kc < NKC; kc++) {
            int cc = p * NKC + kc;
            if (cc > 0) {
                // wait<1>: stages cc AND cc+1 resident (enables tail preload)
                cp_wait<1>();
                __syncthreads();              // releases buffer (cc-1)&3
            }
            const uint32_t st = sb + (cc & 3) * STG;
            const uint32_t st_next = sb + ((cc + 1) & 3) * STG;
#pragma unroll
            for (int kkk = 0; kkk < 8; kkk++) {
                const int cur = kkk & 1;
                if (kkk < 7)
                    load_frags(st, kkk + 1, a_f[cur ^ 1], b_f[cur ^ 1]);
                else if (cc + 1 < NCH)
                    // preload next chunk's first frags; buffer (cc+1)&3 holds
                    // stage cc+1 (guaranteed by wait<1> + barrier), and current
                    // in-flight issue targets (cc-1)&3 != (cc+1)&3
                    load_frags(st_next, 0, a_f[cur ^ 1], b_f[cur ^ 1]);
#pragma unroll
                for (int mi = 0; mi < 2; mi++)
#pragma unroll
                    for (int nj = 0; nj < 2; nj++) {
                        mma_f16(acc[mi][nj * 2],     a_f[cur][mi], &b_f[cur][nj][0]);
                        mma_f16(acc[mi][nj * 2 + 1], a_f[cur][mi], &b_f[cur][nj][2]);
                    }
                if (kkk == 3 && cc + 3 < NCH) issue_stage(cc + 3, (cc + 3) & 3);
            }
        }

        // inverse-transform coefficients for point p = (i,j)
        int pi_ = p >> 2, pj = p & 3;
        float ca0 = (pi_ == 3) ? 0.f : 1.f;                       // At row0 = 1,1,1,0
        float ca1 = (pi_ == 0) ? 0.f : ((pi_ == 1) ? 1.f : -1.f); // At row1 = 0,1,-1,-1
        float cb0 = (pj  == 3) ? 0.f : 1.f;
        float cb1 = (pj  == 0) ? 0.f : ((pj  == 1) ? 1.f : -1.f);
        float c00 = ca0 * cb0, c01 = ca0 * cb1, c10 = ca1 * cb0, c11 = ca1 * cb1;
#pragma unroll
        for (int mi = 0; mi < 2; mi++)
#pragma unroll
            for (int j = 0; j < 4; j++)
#pragma unroll
                for (int v = 0; v < 4; v++) {
                    float m = acc[mi][j][v];
                    outr[mi][j][v][0] += c00 * m;
                    outr[mi][j][v][1] += c01 * m;
                    outr[mi][j][v][2] += c10 * m;
                    outr[mi][j][v][3] += c11 * m;
                }
    }

    // ---- epilogue: outr -> pre2[4 imgs][128][66], then LSTM ----
    __syncthreads();
    float* pre2 = (float*)smem;
    const int lr = lane >> 2, lc = (lane & 3) * 2;
#pragma unroll
    for (int mi = 0; mi < 2; mi++)
#pragma unroll
        for (int j = 0; j < 4; j++)
#pragma unroll
            for (int v = 0; v < 4; v++) {
                int nj = j >> 1, s = j & 1;
                int row = wm * 32 + mi * 16 + lr + ((v >> 1) << 3);
                int col = wn * 32 + nj * 16 + s * 8 + lc + (v & 1);
                int img = col >> 4, t = col & 15;
                int ty = t >> 2, tx = t & 3;
                float* dst = &pre2[((img * 128) + row) * 66 + (2 * ty) * 8 + 2 * tx];
                dst[0] = outr[mi][j][v][0];
                dst[1] = outr[mi][j][v][1];
                dst[8] = outr[mi][j][v][2];
                dst[9] = outr[mi][j][v][3];
            }
    __syncthreads();

    const size_t base2 = (size_t)NB * DH * 64;
    for (int e = tid; e < 4 * 32 * 64; e += GT) {
        int img = e >> 11, cl = (e >> 6) & 31, pix = e & 63;
        int n = nt * 4 + img;
        int c = mt * 32 + cl;
        const float* pr = &pre2[(size_t)img * 128 * 66];
        const float* c0p = hs + ((size_t)(n * 2) + 1) * DH * 64;
        float pi = pr[(cl)      * 66 + pix] + bi[c];
        float pf = pr[(32 + cl) * 66 + pix] + bf_[c];
        float pg = pr[(64 + cl) * 66 + pix] + bg[c];
        float po = pr[(96 + cl) * 66 + pix] + bo[c];
        float c0 = c0p[(size_t)c * 64 + pix];
        float ig = 1.f / (1.f + expf(-(pi + c0 * wci[c * 64 + pix])));
        float fg = 1.f / (1.f + expf(-(pf + c0 * wcf[c * 64 + pix])));
        float gg = tanhf(pg);
        float ct = fg * c0 + ig * gg;
        float og = 1.f / (1.f + expf(-(po + ct * wco[c * 64 + pix])));
        float ht = og * tanhf(ct);
        out[((size_t)n * DH + c) * 64 + pix] = og;
        out[base2 + (((size_t)n * 2) * DH + c) * 64 + pix] = ht;
        out[base2 + (((size_t)n * 2 + 1) * DH + c) * 64 + pix] = ct;
    }
}

extern "C" void kernel_launch(void* const* d_in, const int* in_sizes, int n_in,
                              void* d_out, int out_size) {
    (void)in_sizes; (void)n_in; (void)out_size;
    const float* x  = (const float*)d_in[0];
    const float* hs = (const float*)d_in[1];

    cudaFuncSetAttribute(gemm_fused, cudaFuncAttributeMaxDynamicSharedMemorySize,
                         SMEM_BYTES);

    prep_all<<<PREPA_BLOCKS + PREPB_BLOCKS, 256>>>(
        x, hs,
        (const float*)d_in[2], (const float*)d_in[3], (const float*)d_in[4],
        (const float*)d_in[5], (const float*)d_in[6], (const float*)d_in[7],
        (const float*)d_in[8], (const float*)d_in[9]);

    dim3 grid(MTOT / 128, NT2 / 64);   // 16 x 64 = 1024 CTAs
    gemm_fused<<<grid, GT, SMEM_BYTES>>>(
        hs,
        (const float*)d_in[10], (const float*)d_in[11],
        (const float*)d_in[12], (const float*)d_in[13],
        (const float*)d_in[14], (const float*)d_in[15], (const float*)d_in[16],
        (float*)d_out);
}